// round 3
// baseline (speedup 1.0000x reference)
#include <cuda_runtime.h>

// ---------------------------------------------------------------------------
// QuadraticConv2DTranspose, parity-decomposed.
// B=8, H=W=32, CIN=COUT=64, k=3, s=2  ->  out [8,64,64,64]
//
// Bed-of-nails upsample => each output pixel's 3x3 patch has <=4 nonzero
// entries selected by (ho%2, wo%2). Per parity class we need only
// t in {2,5,5,14} features per input channel (quad+linear); the bias feature
// collapses to a per-cout constant. Work: 4 GEMMs, M=8192, N=64,
// K = t*64 in {128,320,320,896}  => 872 M MACs (vs 7.4G naive).
// ---------------------------------------------------------------------------

#define NB   8
#define HH   32
#define WW   32
#define NC   64    // CIN == COUT

// scratch (static device globals: allocation-free)
__device__ float g_xT[NB * NC * HH * WW];   // [b][c][h][w]
__device__ float g_W [26 * NC * NC];        // packed class weights, row-major (row, o)
__device__ float g_bias[NC];

// l-indices (into the 55-long feature axis of flat_kernel) per class, in the
// exact order the main kernel emits features.
// qidx(i,j) = i*9 - i*(i-1)/2 + (j-i); lin(i) = 45+i; bias = 54.
__constant__ int c_l_idx[26] = {
    // class 0 (even,even): patch {4}
    30, 49,
    // class 1 (even,odd): patch {3,5}
    24, 26, 35, 48, 50,
    // class 2 (odd,even): patch {1,7}
    9, 15, 42, 46, 52,
    // class 3 (odd,odd): patch {0,2,6,8}
    0, 2, 6, 8, 17, 21, 23, 39, 41, 44, 45, 47, 51, 53
};

// ---------------------------------------------------------------------------
// Prep 1: NHWC -> [b][c][h][w] transpose (smem-tiled, conflict-free)
// ---------------------------------------------------------------------------
__global__ void __launch_bounds__(256) xpose_kernel(const float* __restrict__ x)
{
    __shared__ float tile[NC][WW + 1];
    const int bh = blockIdx.x;            // 0..255  => (b,h)
    const int b  = bh >> 5;
    const int h  = bh & 31;
    const float* src = x + (size_t)(b * HH + h) * WW * NC;
    const int tid = threadIdx.x;

    // load: consecutive tid -> consecutive c (coalesced)
    #pragma unroll
    for (int i = tid; i < WW * NC; i += 256) {
        const int w = i >> 6;
        const int c = i & 63;
        tile[c][w] = src[i];
    }
    __syncthreads();
    // store: consecutive tid -> consecutive w (coalesced)
    #pragma unroll
    for (int i = tid; i < WW * NC; i += 256) {
        const int c = i >> 5;
        const int w = i & 31;
        g_xT[((b * NC + c) * HH + h) * WW + w] = tile[c][w];
    }
}

// ---------------------------------------------------------------------------
// Prep 2: gather flat_kernel[l,c,o] into packed per-class weights.
// Layout: class blocks of rows; within a class, row = c*t + tt; 64 o's per row.
// Row offsets: cls0 [0,128), cls1 [128,448), cls2 [448,768), cls3 [768,1664).
// ---------------------------------------------------------------------------
__global__ void __launch_bounds__(256) prepw_kernel(const float* __restrict__ fk)
{
    const int idx = blockIdx.x * 256 + threadIdx.x;
    if (idx >= 1664 * 64) return;
    const int row = idx >> 6;
    const int o   = idx & 63;

    int cls, rr;
    if      (row < 128) { cls = 0; rr = row;       }
    else if (row < 448) { cls = 1; rr = row - 128; }
    else if (row < 768) { cls = 2; rr = row - 448; }
    else                { cls = 3; rr = row - 768; }

    const int tarr[4] = {2, 5, 5, 14};
    const int tb[4]   = {0, 2, 7, 12};
    const int t  = tarr[cls];
    const int c  = rr / t;
    const int tt = rr - c * t;
    const int l  = c_l_idx[tb[cls] + tt];
    g_W[idx] = fk[(l * 64 + c) * 64 + o];
}

__global__ void prepbias_kernel(const float* __restrict__ fk)
{
    const int o = threadIdx.x;   // 64 threads
    float s = 0.f;
    #pragma unroll 8
    for (int c = 0; c < NC; ++c)
        s += fk[(54 * 64 + c) * 64 + o];
    g_bias[o] = s;
}

// ---------------------------------------------------------------------------
// Main: per (class, 64-position tile) block. 128 threads.
// Register tile: 8 positions x 4 couts per thread (32 accumulators).
// Per channel step: threads 0..63 build A[t][64] features in smem,
// threads 64..127 stage B[t][64] weights; then fully-unrolled t-loop FMAs.
// ---------------------------------------------------------------------------
template <int CLS, int T>
__device__ __forceinline__ void qct_body(float* __restrict__ out,
                                         float* __restrict__ As,   // [T][64]
                                         float* __restrict__ Bs)   // [T][64]
{
    const int tid = threadIdx.x;
    const int bx  = blockIdx.x;           // 0..127 position tiles
    const int b   = bx >> 4;              // batch
    const int a0  = (bx & 15) * 2;        // this tile covers input rows a0, a0+1
    const int tx  = tid & 15;             // cout group: o = tx*4 .. tx*4+3
    const int ty  = tid >> 4;             // position group: p = ty*8 .. ty*8+7
    constexpr int oy = CLS >> 1;
    constexpr int ox = CLS & 1;
    constexpr int WROW0 = (CLS == 0 ? 0 : CLS == 1 ? 128 : CLS == 2 ? 448 : 768);

    float acc[8][4];
    #pragma unroll
    for (int i = 0; i < 8; ++i)
        #pragma unroll
        for (int j = 0; j < 4; ++j) acc[i][j] = 0.f;

    // phase-A per-thread position (threads 0..63)
    const int pa  = a0 + (tid >> 5);      // x row
    const int pbc = tid & 31;             // x col
    const float* xb = g_xT + (size_t)b * NC * HH * WW;
    const float* wc = g_W + (size_t)WROW0 * 64;

    for (int c = 0; c < NC; ++c) {
        if (tid < 64) {
            const float* xc = xb + c * (HH * WW) + pa * WW + pbc;
            const float v0 = xc[0];
            float f[T];
            if (CLS == 0) {
                f[0] = v0 * v0; f[1] = v0;
            } else if (CLS == 1) {
                const float v1 = (pbc < 31) ? xc[1] : 0.f;
                f[0] = v0 * v0; f[1] = v0 * v1; f[2] = v1 * v1;
                f[3] = v0; f[4] = v1;
            } else if (CLS == 2) {
                const float v1 = (pa < 31) ? xc[WW] : 0.f;
                f[0] = v0 * v0; f[1] = v0 * v1; f[2] = v1 * v1;
                f[3] = v0; f[4] = v1;
            } else {
                const float v1 = (pbc < 31) ? xc[1] : 0.f;
                const float v2 = (pa < 31) ? xc[WW] : 0.f;
                const float v3 = (pa < 31 && pbc < 31) ? xc[WW + 1] : 0.f;
                f[0] = v0 * v0; f[1] = v0 * v1; f[2] = v0 * v2; f[3] = v0 * v3;
                f[4] = v1 * v1; f[5] = v1 * v2; f[6] = v1 * v3;
                f[7] = v2 * v2; f[8] = v2 * v3; f[9] = v3 * v3;
                f[10] = v0; f[11] = v1; f[12] = v2; f[13] = v3;
            }
            #pragma unroll
            for (int tt = 0; tt < T; ++tt) As[tt * 64 + tid] = f[tt];
        } else {
            const int lt = tid - 64;
            const float* wp = wc + (size_t)c * (T * 64);
            #pragma unroll
            for (int i = lt; i < T * 64; i += 64) Bs[i] = wp[i];
        }
        __syncthreads();

        #pragma unroll
        for (int tt = 0; tt < T; ++tt) {
            const float4 A0 = *(const float4*)&As[tt * 64 + ty * 8];
            const float4 A1 = *(const float4*)&As[tt * 64 + ty * 8 + 4];
            const float4 Bv = *(const float4*)&Bs[tt * 64 + tx * 4];
            const float av[8] = {A0.x, A0.y, A0.z, A0.w, A1.x, A1.y, A1.z, A1.w};
            const float bv[4] = {Bv.x, Bv.y, Bv.z, Bv.w};
            #pragma unroll
            for (int i = 0; i < 8; ++i)
                #pragma unroll
                for (int j = 0; j < 4; ++j)
                    acc[i][j] = fmaf(av[i], bv[j], acc[i][j]);
        }
        __syncthreads();
    }

    // epilogue: add bias constant, float4 store (fully coalesced in o)
    const float4 bias = *(const float4*)&g_bias[tx * 4];
    #pragma unroll
    for (int pp = 0; pp < 8; ++pp) {
        const int p  = ty * 8 + pp;
        const int a  = a0 + (p >> 5);
        const int bc = p & 31;
        const int ho = 2 * a + oy;
        const int wo = 2 * bc + ox;
        float4 r;
        r.x = acc[pp][0] + bias.x;
        r.y = acc[pp][1] + bias.y;
        r.z = acc[pp][2] + bias.z;
        r.w = acc[pp][3] + bias.w;
        *(float4*)&out[((size_t)((b * 64 + ho) * 64 + wo)) * 64 + tx * 4] = r;
    }
}

__global__ void __launch_bounds__(128) qct_main(float* __restrict__ out)
{
    __shared__ float As[14 * 64];
    __shared__ float Bs[14 * 64];
    switch (blockIdx.y) {
        case 0: qct_body<0, 2>(out, As, Bs);  break;
        case 1: qct_body<1, 5>(out, As, Bs);  break;
        case 2: qct_body<2, 5>(out, As, Bs);  break;
        default: qct_body<3, 14>(out, As, Bs); break;
    }
}

// ---------------------------------------------------------------------------
extern "C" void kernel_launch(void* const* d_in, const int* in_sizes, int n_in,
                              void* d_out, int out_size)
{
    const float* x  = (const float*)d_in[0];   // [8,32,32,64]
    const float* fk = (const float*)d_in[1];   // [1,1,55,64,64]
    float* out = (float*)d_out;                // [8,64,64,64]

    xpose_kernel<<<NB * HH, 256>>>(x);
    prepw_kernel<<<(1664 * 64 + 255) / 256, 256>>>(fk);
    prepbias_kernel<<<1, 64>>>(fk);
    qct_main<<<dim3(128, 4), 128>>>(out);
}

// round 4
// speedup vs baseline: 2.7607x; 2.7607x over previous
#include <cuda_runtime.h>
#include <cstdint>

// ---------------------------------------------------------------------------
// QuadraticConv2DTranspose, parity-decomposed.
// B=8, H=W=32, CIN=COUT=64, k=3, s=2  ->  out [8,64,64,64]
//
// Bed-of-nails upsample => each output pixel's 3x3 patch has <=4 nonzero
// entries selected by (ho%2, wo%2). Per parity class only t in {2,5,5,14}
// features per input channel matter; the bias feature collapses to a
// per-cout constant. Work: 4 GEMMs, M=8192, N=64, K = t*64 in
// {128,320,320,896} => 872 M MACs.
//
// R3 redesign: x slab staged in smem once per block (kills per-channel LDG
// latency + the global transpose kernel), channel-chunked mainloop with
// cp.async double-buffered weights, all 128 threads active in every phase.
// ---------------------------------------------------------------------------

#define NB   8
#define HH   32
#define WW   32
#define NC   64    // CIN == COUT

// scratch (static device globals: allocation-free)
__device__ float g_W [26 * NC * NC];        // packed class weights [c][t][64]
__device__ float g_bias[NC];

// l-indices (into the 55-long feature axis) per class, in emission order.
__constant__ int c_l_idx[26] = {
    // class 0 (even,even): patch {4}
    30, 49,
    // class 1 (even,odd): patch {3,5}
    24, 26, 35, 48, 50,
    // class 2 (odd,even): patch {1,7}
    9, 15, 42, 46, 52,
    // class 3 (odd,odd): patch {0,2,6,8}
    0, 2, 6, 8, 17, 21, 23, 39, 41, 44, 45, 47, 51, 53
};

// ---------------------------------------------------------------------------
// Prep: gather flat_kernel[l,c,o] into packed per-class weights.
// Row offsets: cls0 [0,128), cls1 [128,448), cls2 [448,768), cls3 [768,1664).
// ---------------------------------------------------------------------------
__global__ void __launch_bounds__(256) prepw_kernel(const float* __restrict__ fk)
{
    const int idx = blockIdx.x * 256 + threadIdx.x;
    if (idx >= 1664 * 64) return;
    const int row = idx >> 6;
    const int o   = idx & 63;

    int cls, rr;
    if      (row < 128) { cls = 0; rr = row;       }
    else if (row < 448) { cls = 1; rr = row - 128; }
    else if (row < 768) { cls = 2; rr = row - 448; }
    else                { cls = 3; rr = row - 768; }

    const int tarr[4] = {2, 5, 5, 14};
    const int tb[4]   = {0, 2, 7, 12};
    const int t  = tarr[cls];
    const int c  = rr / t;
    const int tt = rr - c * t;
    const int l  = c_l_idx[tb[cls] + tt];
    g_W[idx] = fk[(l * 64 + c) * 64 + o];
}

__global__ void prepbias_kernel(const float* __restrict__ fk)
{
    const int o = threadIdx.x;   // 64 threads
    float s = 0.f;
    #pragma unroll 8
    for (int c = 0; c < NC; ++c)
        s += fk[(54 * 64 + c) * 64 + o];
    g_bias[o] = s;
}

// ---------------------------------------------------------------------------
// cp.async helpers
// ---------------------------------------------------------------------------
__device__ __forceinline__ void cp_async16(uint32_t saddr, const float* g)
{
    asm volatile("cp.async.ca.shared.global [%0], [%1], 16;\n"
                 :: "r"(saddr), "l"(g));
}
__device__ __forceinline__ void cp_commit()
{
    asm volatile("cp.async.commit_group;\n" ::: "memory");
}
__device__ __forceinline__ void cp_wait1()
{
    asm volatile("cp.async.wait_group 1;\n" ::: "memory");
}

// ---------------------------------------------------------------------------
// Main kernel. Grid (128, 4): blockIdx.x = (b, row-pair), blockIdx.y = class.
// 128 threads. Per-thread register tile: 8 positions x 4 couts.
//
// smem: xs [64 ch][3 rows][33 cols] (zero-padded)  = 25344 B
//       As [CH*T][64 positions]                    <= 7168 B
//       Bs [2][CH*T][64 couts] (double buffer)     <= 14336 B
// Total 46848 B (static, < 48 KB).
// ---------------------------------------------------------------------------
#define XS_C 99    // 3*33 floats per channel

template <int CLS, int T, int CH>
__device__ __forceinline__ void qct_body(const float* __restrict__ x,
                                         float* __restrict__ out,
                                         float* __restrict__ xs,
                                         float* __restrict__ As,
                                         float* __restrict__ Bs0,
                                         float* __restrict__ Bs1)
{
    constexpr int CHT    = CH * T;
    constexpr int NCHUNK = NC / CH;
    constexpr int oy = CLS >> 1;
    constexpr int ox = CLS & 1;
    constexpr int WROW0 = (CLS == 0 ? 0 : CLS == 1 ? 128 : CLS == 2 ? 448 : 768);

    const int tid = threadIdx.x;
    const int bx  = blockIdx.x;           // 0..127 position tiles
    const int b   = bx >> 4;              // batch
    const int a0  = (bx & 15) * 2;        // input rows a0, a0+1
    const int tx  = tid & 15;             // cout group: o = tx*4 .. tx*4+3
    const int ty  = tid >> 4;             // position group: p = ty*8 .. ty*8+7

    // ---- stage x slab: rows a0..a0+2 (zero-padded row/col) ----------------
    for (int i = tid; i < NC * XS_C; i += 128) xs[i] = 0.f;
    __syncthreads();
    {
        const int nr = (a0 == 30) ? 2 : 3;            // row 32 doesn't exist
        const float* src = x + (size_t)((b * HH + a0) * WW) * NC;
        for (int i = tid; i < nr * (WW * NC); i += 128) {
            const int r = i >> 11;                    // /2048
            const int rem = i & 2047;
            const int w = rem >> 6;
            const int c = rem & 63;
            xs[c * XS_C + r * 33 + w] = src[i];       // coalesced over c
        }
    }

    // ---- prefetch weight chunk 0 ------------------------------------------
    const float* wsrc = g_W + (size_t)WROW0 * 64;
    {
        uint32_t s = (uint32_t)__cvta_generic_to_shared(Bs0);
        #pragma unroll
        for (int i = tid; i < CHT * 16; i += 128)
            cp_async16(s + i * 16, wsrc + i * 4);
        cp_commit();
    }
    __syncthreads();   // xs visible to all

    float acc[8][4];
    #pragma unroll
    for (int i = 0; i < 8; ++i)
        #pragma unroll
        for (int j = 0; j < 4; ++j) acc[i][j] = 0.f;

    // feature-compute coords for this thread
    const int pos  = tid & 63;
    const int half = tid >> 6;            // channel parity this thread covers
    const int pa   = pos >> 5;            // relative x row (0/1)
    const int pw   = pos & 31;            // x col

    float* Bcur = Bs0;
    float* Bnxt = Bs1;

    #pragma unroll 1
    for (int chunk = 0; chunk < NCHUNK; ++chunk) {
        const int c0 = chunk * CH;

        // ---- build features As[cc*T+tt][pos] for CH channels --------------
        #pragma unroll
        for (int k = 0; k < CH / 2; ++k) {
            const int cc = half + 2 * k;
            const float* xc = xs + (c0 + cc) * XS_C + pa * 33 + pw;
            const float v0 = xc[0];
            float f[T];
            if (CLS == 0) {
                f[0] = v0 * v0; f[1] = v0;
            } else if (CLS == 1) {
                const float v1 = xc[1];
                f[0] = v0 * v0; f[1] = v0 * v1; f[2] = v1 * v1;
                f[3] = v0; f[4] = v1;
            } else if (CLS == 2) {
                const float v1 = xc[33];
                f[0] = v0 * v0; f[1] = v0 * v1; f[2] = v1 * v1;
                f[3] = v0; f[4] = v1;
            } else {
                const float v1 = xc[1];
                const float v2 = xc[33];
                const float v3 = xc[34];
                f[0] = v0 * v0; f[1] = v0 * v1; f[2] = v0 * v2; f[3] = v0 * v3;
                f[4] = v1 * v1; f[5] = v1 * v2; f[6] = v1 * v3;
                f[7] = v2 * v2; f[8] = v2 * v3; f[9] = v3 * v3;
                f[10] = v0; f[11] = v1; f[12] = v2; f[13] = v3;
            }
            #pragma unroll
            for (int tt = 0; tt < T; ++tt)
                As[(cc * T + tt) * 64 + pos] = f[tt];
        }

        // ---- prefetch next weight chunk into the other buffer -------------
        if (chunk + 1 < NCHUNK) {
            const float* wn = wsrc + (size_t)(chunk + 1) * (CHT * 64);
            uint32_t s = (uint32_t)__cvta_generic_to_shared(Bnxt);
            #pragma unroll
            for (int i = tid; i < CHT * 16; i += 128)
                cp_async16(s + i * 16, wn + i * 4);
        }
        cp_commit();
        cp_wait1();          // current chunk's weights have landed
        __syncthreads();     // As + Bcur visible block-wide

        // ---- FMA phase: 32 accs x CHT rows ---------------------------------
        #pragma unroll
        for (int rt = 0; rt < CHT; ++rt) {
            const float4 A0 = *(const float4*)&As[rt * 64 + ty * 8];
            const float4 A1 = *(const float4*)&As[rt * 64 + ty * 8 + 4];
            const float4 Bv = *(const float4*)&Bcur[rt * 64 + tx * 4];
            const float av[8] = {A0.x, A0.y, A0.z, A0.w, A1.x, A1.y, A1.z, A1.w};
            const float bv[4] = {Bv.x, Bv.y, Bv.z, Bv.w};
            #pragma unroll
            for (int i = 0; i < 8; ++i)
                #pragma unroll
                for (int j = 0; j < 4; ++j)
                    acc[i][j] = fmaf(av[i], bv[j], acc[i][j]);
        }
        __syncthreads();     // before As is rewritten / Bnxt refilled

        float* tmp = Bcur; Bcur = Bnxt; Bnxt = tmp;
    }

    // ---- epilogue: add bias, float4 stores (coalesced in o) ---------------
    const float4 bias = *(const float4*)&g_bias[tx * 4];
    #pragma unroll
    for (int pp = 0; pp < 8; ++pp) {
        const int p  = ty * 8 + pp;
        const int a  = a0 + (p >> 5);
        const int bc = p & 31;
        const int ho = 2 * a + oy;
        const int wo = 2 * bc + ox;
        float4 r;
        r.x = acc[pp][0] + bias.x;
        r.y = acc[pp][1] + bias.y;
        r.z = acc[pp][2] + bias.z;
        r.w = acc[pp][3] + bias.w;
        *(float4*)&out[((size_t)((b * 64 + ho) * 64 + wo)) * 64 + tx * 4] = r;
    }
}

__global__ void __launch_bounds__(128) qct_main(const float* __restrict__ x,
                                                float* __restrict__ out)
{
    __shared__ float xs[NC * XS_C];      // 25344 B
    __shared__ float As[28 * 64];        //  7168 B
    __shared__ float Bs[2][28 * 64];     // 14336 B
    switch (blockIdx.y) {
        case 0: qct_body<0, 2, 8>(x, out, xs, As, Bs[0], Bs[1]);  break;
        case 1: qct_body<1, 5, 4>(x, out, xs, As, Bs[0], Bs[1]);  break;
        case 2: qct_body<2, 5, 4>(x, out, xs, As, Bs[0], Bs[1]);  break;
        default: qct_body<3, 14, 2>(x, out, xs, As, Bs[0], Bs[1]); break;
    }
}

// ---------------------------------------------------------------------------
extern "C" void kernel_launch(void* const* d_in, const int* in_sizes, int n_in,
                              void* d_out, int out_size)
{
    const float* x  = (const float*)d_in[0];   // [8,32,32,64]
    const float* fk = (const float*)d_in[1];   // [1,1,55,64,64]
    float* out = (float*)d_out;                // [8,64,64,64]

    prepw_kernel<<<(1664 * 64 + 255) / 256, 256>>>(fk);
    prepbias_kernel<<<1, 64>>>(fk);
    qct_main<<<dim3(128, 4), 128>>>(x, out);
}